// round 9
// baseline (speedup 1.0000x reference)
#include <cuda_runtime.h>
#include <cstdint>
#include <cfloat>

#define MAXN 50000
#define MAXE 800000
#define FEAT 64
#define STRIP 8

// ---------------- scratch (no allocations allowed) ----------------
__device__ float    g_buf[MAXN * FEAT];   // g = dinv * (x @ W)
__device__ float    g_agg[MAXN * FEAT];   // self-loop init + edge accumulation
__device__ float    g_dinv[MAXN];
__device__ int      g_cnt[MAXN];
__device__ int      g_rowptr[MAXN + 1];
__device__ int2     g_epack[MAXE];        // dst-sorted (src, dst) pairs, int32
__device__ int      g_rank[MAXE];         // edge's arrival rank within its dst
__device__ int      g_bsum[256];
__device__ unsigned g_gmax[192];          // order-encoded float max per column
__device__ int      g_is32;               // 1 if edge_index is int32

// ---------------- helpers ----------------
__device__ __forceinline__ unsigned long long pack2(float x, float y) {
    unsigned long long u;
    asm("mov.b64 %0, {%1, %2};" : "=l"(u) : "f"(x), "f"(y));
    return u;
}
__device__ __forceinline__ void unpack2(unsigned long long u, float& x, float& y) {
    asm("mov.b64 {%0, %1}, %2;" : "=f"(x), "=f"(y) : "l"(u));
}
__device__ __forceinline__ unsigned long long ffma2(unsigned long long a,
                                                    unsigned long long b,
                                                    unsigned long long c) {
    unsigned long long d;
    asm("fma.rn.f32x2 %0, %1, %2, %3;" : "=l"(d) : "l"(a), "l"(b), "l"(c));
    return d;
}
__device__ __forceinline__ unsigned ford(float f) {
    unsigned u = __float_as_uint(f);
    return (u & 0x80000000u) ? ~u : (u | 0x80000000u);
}
__device__ __forceinline__ float funord(unsigned v) {
    unsigned b = (v & 0x80000000u) ? (v ^ 0x80000000u) : ~v;
    return __uint_as_float(b);
}
__device__ __forceinline__ int edge_at(const void* ei, int E, int which, int e) {
    if (g_is32) return ((const int*)ei)[(size_t)which * E + e];
    return (int)((const long long*)ei)[(size_t)which * E + e];
}
__device__ __forceinline__ void redv4(float* p, float4 v) {
    asm volatile("red.global.add.v4.f32 [%0], {%1,%2,%3,%4};"
                 :: "l"(p), "f"(v.x), "f"(v.y), "f"(v.z), "f"(v.w) : "memory");
}

// ---------------- preprocessing ----------------
__global__ void init_kernel(int N, int E, const void* ei) {
    int i = blockIdx.x * blockDim.x + threadIdx.x;
    if (i < N) g_cnt[i] = 0;
    if (i < 192) g_gmax[i] = 0u;
    if (i == 0) g_rowptr[N] = E;
    if (blockIdx.x == 0 && threadIdx.x < 32) {
        unsigned long long v = (unsigned long long)((const long long*)ei)[threadIdx.x];
        unsigned m = __ballot_sync(0xffffffffu, (v >> 32) != 0ull);
        if (threadIdx.x == 0) g_is32 = (m != 0u) ? 1 : 0;
    }
}

// count in-degree; the atomic's return value IS the edge's rank within its dst
__global__ void count_kernel(const void* __restrict__ ei, int E) {
    int i = blockIdx.x * blockDim.x + threadIdx.x;
    if (i >= E) return;
    g_rank[i] = atomicAdd(&g_cnt[edge_at(ei, E, 1, i)], 1);
}

// dinv + per-block exclusive scan of counts (coalesced, tile 256)
__global__ void scan1_kernel(int N) {
    int t = threadIdx.x;
    int i = blockIdx.x * 256 + t;
    int c = (i < N) ? g_cnt[i] : 0;
    if (i < N) g_dinv[i] = rsqrtf((float)(c + 1));
    __shared__ int sh[256];
    sh[t] = c;
    __syncthreads();
    for (int off = 1; off < 256; off <<= 1) {
        int u = (t >= off) ? sh[t - off] : 0;
        __syncthreads();
        sh[t] += u;
        __syncthreads();
    }
    if (i < N) g_rowptr[i] = sh[t] - c;
    if (t == 255) g_bsum[blockIdx.x] = sh[255];
}

// every block redundantly scans the <=256 block sums in smem, then offsets its tile
__global__ void scan23_kernel(int N, int nblocks) {
    int t = threadIdx.x;
    __shared__ int sh[256];
    int c = (t < nblocks) ? g_bsum[t] : 0;
    sh[t] = c;
    __syncthreads();
    for (int off = 1; off < 256; off <<= 1) {
        int u = (t >= off) ? sh[t - off] : 0;
        __syncthreads();
        sh[t] += u;
        __syncthreads();
    }
    int base = sh[blockIdx.x] - ((blockIdx.x < nblocks) ? g_bsum[blockIdx.x] : 0);
    int i = blockIdx.x * 256 + t;
    if (i < N) g_rowptr[i] += base;
}

// dst-sorted packed edges, atomic-free: slot = rowptr[dst] + rank[edge]
__global__ void fill_kernel(const void* __restrict__ ei, int E) {
    int e = blockIdx.x * blockDim.x + threadIdx.x;
    if (e >= E) return;
    int s = edge_at(ei, E, 0, e);
    int d = edge_at(ei, E, 1, e);
    int slot = g_rowptr[d] + g_rank[e];
    g_epack[slot] = make_int2(s, d);
}

// ---------------- GEMM core (shared by standalone + fused) ----------------
// writes g_buf = g_agg = dinv * (Xs @ Ws) for rows [row0, row0+64)
__device__ __forceinline__ void gemm_body(const float* Ws, const float* Xs,
                                          int row0, int nrows, int t) {
    int w = t >> 5;
    int l = t & 31;
    unsigned long long acc0[8], acc1[8];
#pragma unroll
    for (int j = 0; j < 8; j++) { acc0[j] = 0ull; acc1[j] = 0ull; }

#pragma unroll 8
    for (int k = 0; k < 64; k++) {
        float2 xv = *(const float2*)&Xs[k * 66 + 2 * l];
        const float4* wp = (const float4*)&Ws[k * 64 + w * 16];
        float4 wa = wp[0], wb = wp[1], wc = wp[2], wd = wp[3];
        unsigned long long x0 = pack2(xv.x, xv.x);
        unsigned long long x1 = pack2(xv.y, xv.y);
        unsigned long long wq[8] = {
            pack2(wa.x, wa.y), pack2(wa.z, wa.w),
            pack2(wb.x, wb.y), pack2(wb.z, wb.w),
            pack2(wc.x, wc.y), pack2(wc.z, wc.w),
            pack2(wd.x, wd.y), pack2(wd.z, wd.w)};
#pragma unroll
        for (int j = 0; j < 8; j++) {
            acc0[j] = ffma2(x0, wq[j], acc0[j]);
            acc1[j] = ffma2(x1, wq[j], acc1[j]);
        }
    }

#pragma unroll
    for (int rr = 0; rr < 2; rr++) {
        int gr = row0 + 2 * l + rr;
        if (gr >= nrows) continue;
        float dv = g_dinv[gr];
        unsigned long long* acc = rr ? acc1 : acc0;
        float o[16];
#pragma unroll
        for (int j = 0; j < 8; j++) {
            unpack2(acc[j], o[2 * j], o[2 * j + 1]);
            o[2 * j] *= dv; o[2 * j + 1] *= dv;
        }
        float4* gp = (float4*)&g_buf[(size_t)gr * FEAT + w * 16];
        float4* ap = (float4*)&g_agg[(size_t)gr * FEAT + w * 16];
#pragma unroll
        for (int j = 0; j < 4; j++) {
            float4 v = make_float4(o[4 * j], o[4 * j + 1], o[4 * j + 2], o[4 * j + 3]);
            gp[j] = v; ap[j] = v;
        }
    }
}

// standalone GEMM (layer 1, reads global X)
__global__ __launch_bounds__(128) void gemm_kernel(
    const float* __restrict__ X, int xstride,
    const float* __restrict__ W, int nrows)
{
    __shared__ float Ws[64 * 64];
    __shared__ float Xs[64 * 66];
    int t = threadIdx.x;
    int row0 = blockIdx.x * 64;
    for (int i = t; i < 4096; i += 128) Ws[i] = W[i];
    for (int i = t; i < 4096; i += 128) {
        int r = i >> 6, k = i & 63;
        int gr = row0 + r;
        Xs[k * 66 + r] = (gr < nrows) ? X[(size_t)gr * xstride + k] : 0.f;
    }
    __syncthreads();
    gemm_body(Ws, Xs, row0, nrows, t);
}

// fused: finalize layer L (relu + out write + colmax) feeding GEMM of layer L+1.
__global__ __launch_bounds__(128) void fused_fg_kernel(
    const float* __restrict__ bias, float* __restrict__ out, int colbase,
    const float* __restrict__ Wn, int N)
{
    __shared__ float Ws[64 * 64];
    __shared__ float Xs[64 * 66];
    __shared__ float sm[128];
    int t = threadIdx.x;
    int row0 = blockIdx.x * 64;

    for (int i = t; i < 4096; i += 128) Ws[i] = Wn[i];

    int c = t & 63;
    float b = bias[c];
    float mx = -FLT_MAX;
    for (int rr = t >> 6; rr < 64; rr += 2) {
        int gr = row0 + rr;
        float val = 0.f;
        if (gr < N) {
            val = fmaf(g_dinv[gr], g_agg[(size_t)gr * FEAT + c], b);
            val = fmaxf(val, 0.f);                       // fused layers always relu
            out[(size_t)gr * 192 + colbase + c] = val;
            mx = fmaxf(mx, val);
        }
        Xs[c * 66 + rr] = val;                           // transposed, ready for GEMM
    }
    sm[t] = mx;
    __syncthreads();                                     // covers Xs, Ws, sm
    if (t < 64) atomicMax(&g_gmax[colbase + t], ford(fmaxf(sm[t], sm[t + 64])));

    gemm_body(Ws, Xs, row0, N, t);
}

// ---------------- strip-mined segmented scatter ----------------
// Thread = (8-edge dst-sorted strip, float4 feature group). Index loads are
// same-address warp broadcasts (L1). Row loads independent (MLP=8); same-dst
// runs reduce in registers; red.global only at run boundaries.
__global__ __launch_bounds__(256) void scatter_kernel(int E) {
    int t = blockIdx.x * 256 + threadIdx.x;
    int grp = t & 15;
    int base = (t >> 4) * STRIP;
    if (base >= E) return;

    int2 sd[STRIP];
#pragma unroll
    for (int j = 0; j < STRIP; j++) {
        int e = base + j;
        sd[j] = (e < E) ? g_epack[e] : make_int2(0, -1);
    }
    float4 v[STRIP];
#pragma unroll
    for (int j = 0; j < STRIP; j++) {
        v[j] = (sd[j].y >= 0)
             ? *(const float4*)&g_buf[(size_t)sd[j].x * FEAT + grp * 4]
             : make_float4(0.f, 0.f, 0.f, 0.f);
    }

    int curd = sd[0].y;
    float4 acc = v[0];
#pragma unroll
    for (int j = 1; j < STRIP; j++) {
        if (sd[j].y == curd) {
            acc.x += v[j].x; acc.y += v[j].y; acc.z += v[j].z; acc.w += v[j].w;
        } else {
            if (curd >= 0) redv4(&g_agg[(size_t)curd * FEAT + grp * 4], acc);
            curd = sd[j].y;
            acc = v[j];
        }
    }
    if (curd >= 0) redv4(&g_agg[(size_t)curd * FEAT + grp * 4], acc);
}

// ---------------- standalone finalize (last layer, no relu) ----------------
__global__ __launch_bounds__(256) void finalize_kernel(
    const float* __restrict__ bias, float* __restrict__ out,
    int colbase, int N)
{
    int t = threadIdx.x;
    int c = t & 63, rg = t >> 6;
    float b = bias[c];
    float mx = -FLT_MAX;
    for (int r = blockIdx.x * 4 + rg; r < N; r += gridDim.x * 4) {
        float v = fmaf(g_dinv[r], g_agg[(size_t)r * FEAT + c], b);
        out[(size_t)r * 192 + colbase + c] = v;
        mx = fmaxf(mx, v);
    }
    __shared__ float sm[256];
    sm[t] = mx;
    __syncthreads();
    if (rg == 0) {
        mx = fmaxf(fmaxf(sm[c], sm[64 + c]), fmaxf(sm[128 + c], sm[192 + c]));
        atomicMax(&g_gmax[colbase + c], ford(mx));
    }
}

// ---------------- tail ----------------
__global__ void tail_kernel(float* __restrict__ out,
                            const float* __restrict__ fcW,
                            const float* __restrict__ fcb,
                            const int* __restrict__ tptr, int N)
{
    int t = threadIdx.x;
    if (t < 192) out[(size_t)N * 192 + t] = funord(g_gmax[t]);
    if (t < 4) {
        int tn = *tptr;
        const float* emb = out + (size_t)tn * 192;
        float s = fcb[t];
        for (int k = 0; k < 192; k++) s += emb[k] * fcW[k * 4 + t];
        out[(size_t)N * 192 + 192 + t] = s;
    }
}

// ---------------- launch ----------------
extern "C" void kernel_launch(void* const* d_in, const int* in_sizes, int n_in,
                              void* d_out, int out_size)
{
    const float* x   = (const float*)d_in[0];
    const void*  ei  = d_in[1];
    const int*   tgt = (const int*)d_in[3];
    const float* W1  = (const float*)d_in[4];
    const float* b1  = (const float*)d_in[5];
    const float* W2  = (const float*)d_in[6];
    const float* b2  = (const float*)d_in[7];
    const float* W3  = (const float*)d_in[8];
    const float* b3  = (const float*)d_in[9];
    const float* fcW = (const float*)d_in[10];
    const float* fcb = (const float*)d_in[11];
    float* out = (float*)d_out;

    int N = in_sizes[0] / FEAT;
    int E = in_sizes[1] / 2;
    int nscan = (N + 255) / 256;

    init_kernel<<<nscan, 256>>>(N, E, ei);
    count_kernel<<<(E + 255) / 256, 256>>>(ei, E);
    scan1_kernel<<<nscan, 256>>>(N);
    scan23_kernel<<<nscan, 256>>>(N, nscan);
    fill_kernel<<<(E + 255) / 256, 256>>>(ei, E);

    int gemm_blocks = (N + 63) / 64;
    int nstrips = (E + STRIP - 1) / STRIP;
    int sc_blocks = (nstrips * 16 + 255) / 256;

    gemm_kernel<<<gemm_blocks, 128>>>(x, FEAT, W1, N);
    scatter_kernel<<<sc_blocks, 256>>>(E);
    fused_fg_kernel<<<gemm_blocks, 128>>>(b1, out, 0, W2, N);
    scatter_kernel<<<sc_blocks, 256>>>(E);
    fused_fg_kernel<<<gemm_blocks, 128>>>(b2, out, 64, W3, N);
    scatter_kernel<<<sc_blocks, 256>>>(E);
    finalize_kernel<<<512, 256>>>(b3, out, 128, N);
    tail_kernel<<<1, 192>>>(out, fcW, fcb, tgt, N);
}

// round 11
// speedup vs baseline: 1.0478x; 1.0478x over previous
#include <cuda_runtime.h>
#include <cstdint>
#include <cfloat>

#define MAXN 50000
#define MAXE 800000
#define FEAT 64
#define STRIP 32
#define CHK 8

// ---------------- scratch (no allocations allowed) ----------------
// Invariants (restored by the kernels that consume them, BSS-zero at load):
//   g_cnt  == 0 on entry (scan1 re-zeroes after reading)
//   g_gmax == 0 on entry (tail re-zeroes after reading)
__device__ float    g_buf[MAXN * FEAT];   // g = dinv * (x @ W)
__device__ float    g_agg[MAXN * FEAT];   // self-loop init + edge accumulation
__device__ float    g_dinv[MAXN];
__device__ int      g_cnt[MAXN];
__device__ int      g_rowptr[MAXN];       // scan intermediate
__device__ int2     g_epack[MAXE];        // dst-sorted (src, dst) pairs, int32
__device__ int      g_pos[MAXN];
__device__ int      g_bsum[256];
__device__ unsigned g_gmax[192];          // order-encoded float max per column

// ---------------- helpers ----------------
__device__ __forceinline__ unsigned long long pack2(float x, float y) {
    unsigned long long u;
    asm("mov.b64 %0, {%1, %2};" : "=l"(u) : "f"(x), "f"(y));
    return u;
}
__device__ __forceinline__ void unpack2(unsigned long long u, float& x, float& y) {
    asm("mov.b64 {%0, %1}, %2;" : "=f"(x), "=f"(y) : "l"(u));
}
__device__ __forceinline__ unsigned long long ffma2(unsigned long long a,
                                                    unsigned long long b,
                                                    unsigned long long c) {
    unsigned long long d;
    asm("fma.rn.f32x2 %0, %1, %2, %3;" : "=l"(d) : "l"(a), "l"(b), "l"(c));
    return d;
}
__device__ __forceinline__ unsigned ford(float f) {
    unsigned u = __float_as_uint(f);
    return (u & 0x80000000u) ? ~u : (u | 0x80000000u);
}
__device__ __forceinline__ float funord(unsigned v) {
    unsigned b = (v & 0x80000000u) ? (v ^ 0x80000000u) : ~v;
    return __uint_as_float(b);
}
// per-block int32-vs-int64 detect: 32 int64 reads of the first 256B of the
// edge buffer; int64 reads of int32 data have nonzero high words.
__device__ __forceinline__ int detect_is32(const void* ei) {
    __shared__ int s32;
    if (threadIdx.x < 32) {
        unsigned long long v = ((const unsigned long long*)ei)[threadIdx.x];
        unsigned m = __ballot_sync(0xffffffffu, (v >> 32) != 0ull);
        if (threadIdx.x == 0) s32 = (m != 0u) ? 1 : 0;
    }
    __syncthreads();
    return s32;
}
__device__ __forceinline__ int edge_at(const void* ei, int E, int which, int e,
                                       int is32) {
    if (is32) return ((const int*)ei)[(size_t)which * E + e];
    return (int)((const long long*)ei)[(size_t)which * E + e];
}
__device__ __forceinline__ void redv4(float* p, float4 v) {
    asm volatile("red.global.add.v4.f32 [%0], {%1,%2,%3,%4};"
                 :: "l"(p), "f"(v.x), "f"(v.y), "f"(v.z), "f"(v.w) : "memory");
}

// ---------------- preprocessing ----------------
// count in-degree (g_cnt is zero on entry by invariant)
__global__ void count_kernel(const void* __restrict__ ei, int E) {
    int is32 = detect_is32(ei);
    int i = blockIdx.x * blockDim.x + threadIdx.x;
    if (i >= E) return;
    atomicAdd(&g_cnt[edge_at(ei, E, 1, i, is32)], 1);
}

// dinv + per-block exclusive scan of counts; re-zeroes g_cnt (invariant)
__global__ void scan1_kernel(int N) {
    int t = threadIdx.x;
    int i = blockIdx.x * 256 + t;
    int c = (i < N) ? g_cnt[i] : 0;
    if (i < N) {
        g_dinv[i] = rsqrtf((float)(c + 1));
        g_cnt[i] = 0;                      // restore invariant for next call
    }
    __shared__ int sh[256];
    sh[t] = c;
    __syncthreads();
    for (int off = 1; off < 256; off <<= 1) {
        int u = (t >= off) ? sh[t - off] : 0;
        __syncthreads();
        sh[t] += u;
        __syncthreads();
    }
    if (i < N) g_rowptr[i] = sh[t] - c;
    if (t == 255) g_bsum[blockIdx.x] = sh[255];
}

// every block redundantly scans the <=256 block sums in smem, then offsets its tile
__global__ void scan23_kernel(int N, int nblocks) {
    int t = threadIdx.x;
    __shared__ int sh[256];
    int c = (t < nblocks) ? g_bsum[t] : 0;
    sh[t] = c;
    __syncthreads();
    for (int off = 1; off < 256; off <<= 1) {
        int u = (t >= off) ? sh[t - off] : 0;
        __syncthreads();
        sh[t] += u;
        __syncthreads();
    }
    int base = sh[blockIdx.x] - ((blockIdx.x < nblocks) ? g_bsum[blockIdx.x] : 0);
    int i = blockIdx.x * 256 + t;
    if (i < N) g_pos[i] = g_rowptr[i] + base;
}

// dst-sorted packed edges (int32)
__global__ void fill_kernel(const void* __restrict__ ei, int E) {
    int is32 = detect_is32(ei);
    int e = blockIdx.x * blockDim.x + threadIdx.x;
    if (e >= E) return;
    int s = edge_at(ei, E, 0, e, is32);
    int d = edge_at(ei, E, 1, e, is32);
    int slot = atomicAdd(&g_pos[d], 1);
    g_epack[slot] = make_int2(s, d);
}

// ---------------- GEMM core (shared by standalone + fused) ----------------
// writes g_buf = g_agg = dinv * (Xs @ Ws) for rows [row0, row0+64)
__device__ __forceinline__ void gemm_body(const float* Ws, const float* Xs,
                                          int row0, int nrows, int t) {
    int w = t >> 5;
    int l = t & 31;
    unsigned long long acc0[8], acc1[8];
#pragma unroll
    for (int j = 0; j < 8; j++) { acc0[j] = 0ull; acc1[j] = 0ull; }

#pragma unroll 8
    for (int k = 0; k < 64; k++) {
        float2 xv = *(const float2*)&Xs[k * 66 + 2 * l];
        const float4* wp = (const float4*)&Ws[k * 64 + w * 16];
        float4 wa = wp[0], wb = wp[1], wc = wp[2], wd = wp[3];
        unsigned long long x0 = pack2(xv.x, xv.x);
        unsigned long long x1 = pack2(xv.y, xv.y);
        unsigned long long wq[8] = {
            pack2(wa.x, wa.y), pack2(wa.z, wa.w),
            pack2(wb.x, wb.y), pack2(wb.z, wb.w),
            pack2(wc.x, wc.y), pack2(wc.z, wc.w),
            pack2(wd.x, wd.y), pack2(wd.z, wd.w)};
#pragma unroll
        for (int j = 0; j < 8; j++) {
            acc0[j] = ffma2(x0, wq[j], acc0[j]);
            acc1[j] = ffma2(x1, wq[j], acc1[j]);
        }
    }

#pragma unroll
    for (int rr = 0; rr < 2; rr++) {
        int gr = row0 + 2 * l + rr;
        if (gr >= nrows) continue;
        float dv = g_dinv[gr];
        unsigned long long* acc = rr ? acc1 : acc0;
        float o[16];
#pragma unroll
        for (int j = 0; j < 8; j++) {
            unpack2(acc[j], o[2 * j], o[2 * j + 1]);
            o[2 * j] *= dv; o[2 * j + 1] *= dv;
        }
        float4* gp = (float4*)&g_buf[(size_t)gr * FEAT + w * 16];
        float4* ap = (float4*)&g_agg[(size_t)gr * FEAT + w * 16];
#pragma unroll
        for (int j = 0; j < 4; j++) {
            float4 v = make_float4(o[4 * j], o[4 * j + 1], o[4 * j + 2], o[4 * j + 3]);
            gp[j] = v; ap[j] = v;
        }
    }
}

// standalone GEMM (layer 1, reads global X)
__global__ __launch_bounds__(128) void gemm_kernel(
    const float* __restrict__ X, int xstride,
    const float* __restrict__ W, int nrows)
{
    __shared__ float Ws[64 * 64];
    __shared__ float Xs[64 * 66];
    int t = threadIdx.x;
    int row0 = blockIdx.x * 64;
    for (int i = t; i < 4096; i += 128) Ws[i] = W[i];
    for (int i = t; i < 4096; i += 128) {
        int r = i >> 6, k = i & 63;
        int gr = row0 + r;
        Xs[k * 66 + r] = (gr < nrows) ? X[(size_t)gr * xstride + k] : 0.f;
    }
    __syncthreads();
    gemm_body(Ws, Xs, row0, nrows, t);
}

// fused: finalize layer L (relu + out write + colmax) feeding GEMM of layer L+1.
__global__ __launch_bounds__(128) void fused_fg_kernel(
    const float* __restrict__ bias, float* __restrict__ out, int colbase,
    const float* __restrict__ Wn, int N)
{
    __shared__ float Ws[64 * 64];
    __shared__ float Xs[64 * 66];
    __shared__ float sm[128];
    int t = threadIdx.x;
    int row0 = blockIdx.x * 64;

    for (int i = t; i < 4096; i += 128) Ws[i] = Wn[i];

    int c = t & 63;
    float b = bias[c];
    float mx = -FLT_MAX;
    for (int rr = t >> 6; rr < 64; rr += 2) {
        int gr = row0 + rr;
        float val = 0.f;
        if (gr < N) {
            val = fmaf(g_dinv[gr], g_agg[(size_t)gr * FEAT + c], b);
            val = fmaxf(val, 0.f);                       // fused layers always relu
            out[(size_t)gr * 192 + colbase + c] = val;
            mx = fmaxf(mx, val);
        }
        Xs[c * 66 + rr] = val;                           // transposed, ready for GEMM
    }
    sm[t] = mx;
    __syncthreads();                                     // covers Xs, Ws, sm
    if (t < 64) atomicMax(&g_gmax[colbase + t], ford(fmaxf(sm[t], sm[t + 64])));

    gemm_body(Ws, Xs, row0, N, t);
}

// ---------------- strip-mined segmented scatter ----------------
// Thread = (32-edge dst-sorted strip, float4 feature group), processed in 4
// chunks of 8 so registers stay at the STRIP=8 level while run compression
// spans 32 edges. Loads within a chunk are independent (MLP=8); same-dst runs
// reduce in registers; red.global only at run boundaries.
__global__ __launch_bounds__(256) void scatter_kernel(int E) {
    int t = blockIdx.x * 256 + threadIdx.x;
    int grp = t & 15;
    int base = (t >> 4) * STRIP;
    if (base >= E) return;

    int curd = -1;
    float4 acc = make_float4(0.f, 0.f, 0.f, 0.f);

    for (int c0 = 0; c0 < STRIP; c0 += CHK) {
        int2 sd[CHK];
#pragma unroll
        for (int j = 0; j < CHK; j++) {
            int e = base + c0 + j;
            sd[j] = (e < E) ? g_epack[e] : make_int2(0, -1);
        }
        float4 v[CHK];
#pragma unroll
        for (int j = 0; j < CHK; j++) {
            v[j] = (sd[j].y >= 0)
                 ? *(const float4*)&g_buf[(size_t)sd[j].x * FEAT + grp * 4]
                 : make_float4(0.f, 0.f, 0.f, 0.f);
        }
#pragma unroll
        for (int j = 0; j < CHK; j++) {
            if (sd[j].y == curd) {
                acc.x += v[j].x; acc.y += v[j].y; acc.z += v[j].z; acc.w += v[j].w;
            } else {
                if (curd >= 0) redv4(&g_agg[(size_t)curd * FEAT + grp * 4], acc);
                curd = sd[j].y;
                acc = v[j];
            }
        }
    }
    if (curd >= 0) redv4(&g_agg[(size_t)curd * FEAT + grp * 4], acc);
}

// ---------------- standalone finalize (last layer, no relu) ----------------
__global__ __launch_bounds__(256) void finalize_kernel(
    const float* __restrict__ bias, float* __restrict__ out,
    int colbase, int N)
{
    int t = threadIdx.x;
    int c = t & 63, rg = t >> 6;
    float b = bias[c];
    float mx = -FLT_MAX;
    for (int r = blockIdx.x * 4 + rg; r < N; r += gridDim.x * 4) {
        float v = fmaf(g_dinv[r], g_agg[(size_t)r * FEAT + c], b);
        out[(size_t)r * 192 + colbase + c] = v;
        mx = fmaxf(mx, v);
    }
    __shared__ float sm[256];
    sm[t] = mx;
    __syncthreads();
    if (rg == 0) {
        mx = fmaxf(fmaxf(sm[c], sm[64 + c]), fmaxf(sm[128 + c], sm[192 + c]));
        atomicMax(&g_gmax[colbase + c], ford(mx));
    }
}

// ---------------- tail: graph_embedding + logits; re-zeroes g_gmax ----------
__global__ void tail_kernel(float* __restrict__ out,
                            const float* __restrict__ fcW,
                            const float* __restrict__ fcb,
                            const int* __restrict__ tptr, int N)
{
    int t = threadIdx.x;
    if (t < 192) {
        out[(size_t)N * 192 + t] = funord(g_gmax[t]);
        g_gmax[t] = 0u;                    // restore invariant for next call
    }
    if (t < 4) {
        int tn = *tptr;
        const float* emb = out + (size_t)tn * 192;
        float s = fcb[t];
        for (int k = 0; k < 192; k++) s += emb[k] * fcW[k * 4 + t];
        out[(size_t)N * 192 + 192 + t] = s;
    }
}

// ---------------- launch ----------------
extern "C" void kernel_launch(void* const* d_in, const int* in_sizes, int n_in,
                              void* d_out, int out_size)
{
    const float* x   = (const float*)d_in[0];
    const void*  ei  = d_in[1];
    const int*   tgt = (const int*)d_in[3];
    const float* W1  = (const float*)d_in[4];
    const float* b1  = (const float*)d_in[5];
    const float* W2  = (const float*)d_in[6];
    const float* b2  = (const float*)d_in[7];
    const float* W3  = (const float*)d_in[8];
    const float* b3  = (const float*)d_in[9];
    const float* fcW = (const float*)d_in[10];
    const float* fcb = (const float*)d_in[11];
    float* out = (float*)d_out;

    int N = in_sizes[0] / FEAT;
    int E = in_sizes[1] / 2;
    int nscan = (N + 255) / 256;

    count_kernel<<<(E + 255) / 256, 256>>>(ei, E);
    scan1_kernel<<<nscan, 256>>>(N);
    scan23_kernel<<<nscan, 256>>>(N, nscan);
    fill_kernel<<<(E + 255) / 256, 256>>>(ei, E);

    int gemm_blocks = (N + 63) / 64;
    int nstrips = (E + STRIP - 1) / STRIP;
    int sc_blocks = (nstrips * 16 + 255) / 256;

    gemm_kernel<<<gemm_blocks, 128>>>(x, FEAT, W1, N);
    scatter_kernel<<<sc_blocks, 256>>>(E);
    fused_fg_kernel<<<gemm_blocks, 128>>>(b1, out, 0, W2, N);
    scatter_kernel<<<sc_blocks, 256>>>(E);
    fused_fg_kernel<<<gemm_blocks, 128>>>(b2, out, 64, W3, N);
    scatter_kernel<<<sc_blocks, 256>>>(E);
    finalize_kernel<<<512, 256>>>(b3, out, 128, N);
    tail_kernel<<<1, 192>>>(out, fcW, fcb, tgt, N);
}

// round 12
// speedup vs baseline: 1.0693x; 1.0205x over previous
#include <cuda_runtime.h>
#include <cstdint>
#include <cfloat>

#define MAXN 50000
#define MAXE 800000
#define FEAT 64
#define STRIP 32
#define CHK 8

// ---------------- scratch (no allocations allowed) ----------------
// Invariants (restored by the kernels that consume them, BSS-zero at load):
//   g_cnt  == 0 on entry (scan1 re-zeroes after reading)
//   g_gmax == 0 on entry (finalize's last block re-zeroes after reading)
//   g_done == 0 on entry (finalize's last block resets)
__device__ float    g_buf[MAXN * FEAT];   // g = dinv * (x @ W)
__device__ float    g_agg[MAXN * FEAT];   // self-loop init + edge accumulation
__device__ float    g_dinv[MAXN];
__device__ int      g_cnt[MAXN];
__device__ int      g_rowptr[MAXN];       // scan intermediate
__device__ int2     g_epack[MAXE];        // dst-sorted (src, dst) pairs, int32
__device__ int      g_pos[MAXN];
__device__ int      g_bsum[256];
__device__ unsigned g_gmax[192];          // order-encoded float max per column
__device__ int      g_done;               // finalize completion counter

// ---------------- helpers ----------------
__device__ __forceinline__ unsigned long long pack2(float x, float y) {
    unsigned long long u;
    asm("mov.b64 %0, {%1, %2};" : "=l"(u) : "f"(x), "f"(y));
    return u;
}
__device__ __forceinline__ void unpack2(unsigned long long u, float& x, float& y) {
    asm("mov.b64 {%0, %1}, %2;" : "=f"(x), "=f"(y) : "l"(u));
}
__device__ __forceinline__ unsigned long long ffma2(unsigned long long a,
                                                    unsigned long long b,
                                                    unsigned long long c) {
    unsigned long long d;
    asm("fma.rn.f32x2 %0, %1, %2, %3;" : "=l"(d) : "l"(a), "l"(b), "l"(c));
    return d;
}
__device__ __forceinline__ unsigned ford(float f) {
    unsigned u = __float_as_uint(f);
    return (u & 0x80000000u) ? ~u : (u | 0x80000000u);
}
__device__ __forceinline__ float funord(unsigned v) {
    unsigned b = (v & 0x80000000u) ? (v ^ 0x80000000u) : ~v;
    return __uint_as_float(b);
}
// per-block int32-vs-int64 detect: 32 int64 reads of the first 256B of the
// edge buffer; int64 reads of int32 data have nonzero high words.
__device__ __forceinline__ int detect_is32(const void* ei) {
    __shared__ int s32;
    if (threadIdx.x < 32) {
        unsigned long long v = ((const unsigned long long*)ei)[threadIdx.x];
        unsigned m = __ballot_sync(0xffffffffu, (v >> 32) != 0ull);
        if (threadIdx.x == 0) s32 = (m != 0u) ? 1 : 0;
    }
    __syncthreads();
    return s32;
}
__device__ __forceinline__ int edge_at(const void* ei, int E, int which, int e,
                                       int is32) {
    if (is32) return ((const int*)ei)[(size_t)which * E + e];
    return (int)((const long long*)ei)[(size_t)which * E + e];
}
__device__ __forceinline__ void redv4(float* p, float4 v) {
    asm volatile("red.global.add.v4.f32 [%0], {%1,%2,%3,%4};"
                 :: "l"(p), "f"(v.x), "f"(v.y), "f"(v.z), "f"(v.w) : "memory");
}

// ---------------- preprocessing ----------------
// count in-degree, 4 edges/thread (independent loads + fire-and-forget REDs)
__global__ void count_kernel(const void* __restrict__ ei, int E) {
    int is32 = detect_is32(ei);
    int e0 = (blockIdx.x * blockDim.x + threadIdx.x) * 4;
    if (e0 >= E) return;
    int d[4];
#pragma unroll
    for (int j = 0; j < 4; j++)
        d[j] = (e0 + j < E) ? edge_at(ei, E, 1, e0 + j, is32) : -1;
#pragma unroll
    for (int j = 0; j < 4; j++)
        if (d[j] >= 0) atomicAdd(&g_cnt[d[j]], 1);
}

// dinv + per-block exclusive scan of counts; re-zeroes g_cnt (invariant)
__global__ void scan1_kernel(int N) {
    int t = threadIdx.x;
    int i = blockIdx.x * 256 + t;
    int c = (i < N) ? g_cnt[i] : 0;
    if (i < N) {
        g_dinv[i] = rsqrtf((float)(c + 1));
        g_cnt[i] = 0;                      // restore invariant for next call
    }
    __shared__ int sh[256];
    sh[t] = c;
    __syncthreads();
    for (int off = 1; off < 256; off <<= 1) {
        int u = (t >= off) ? sh[t - off] : 0;
        __syncthreads();
        sh[t] += u;
        __syncthreads();
    }
    if (i < N) g_rowptr[i] = sh[t] - c;
    if (t == 255) g_bsum[blockIdx.x] = sh[255];
}

// every block redundantly scans the <=256 block sums in smem, then offsets its tile
__global__ void scan23_kernel(int N, int nblocks) {
    int t = threadIdx.x;
    __shared__ int sh[256];
    int c = (t < nblocks) ? g_bsum[t] : 0;
    sh[t] = c;
    __syncthreads();
    for (int off = 1; off < 256; off <<= 1) {
        int u = (t >= off) ? sh[t - off] : 0;
        __syncthreads();
        sh[t] += u;
        __syncthreads();
    }
    int base = sh[blockIdx.x] - ((blockIdx.x < nblocks) ? g_bsum[blockIdx.x] : 0);
    int i = blockIdx.x * 256 + t;
    if (i < N) g_pos[i] = g_rowptr[i] + base;
}

// dst-sorted packed edges, 4 edges/thread (4 independent ATOMG round-trips)
__global__ void fill_kernel(const void* __restrict__ ei, int E) {
    int is32 = detect_is32(ei);
    int e0 = (blockIdx.x * blockDim.x + threadIdx.x) * 4;
    if (e0 >= E) return;
    int s[4], d[4];
#pragma unroll
    for (int j = 0; j < 4; j++) {
        int e = e0 + j;
        if (e < E) {
            s[j] = edge_at(ei, E, 0, e, is32);
            d[j] = edge_at(ei, E, 1, e, is32);
        } else d[j] = -1;
    }
    int slot[4];
#pragma unroll
    for (int j = 0; j < 4; j++)
        if (d[j] >= 0) slot[j] = atomicAdd(&g_pos[d[j]], 1);
#pragma unroll
    for (int j = 0; j < 4; j++)
        if (d[j] >= 0) g_epack[slot[j]] = make_int2(s[j], d[j]);
}

// ---------------- GEMM core (shared by standalone + fused) ----------------
// writes g_buf = g_agg = dinv * (Xs @ Ws) for rows [row0, row0+64)
__device__ __forceinline__ void gemm_body(const float* Ws, const float* Xs,
                                          int row0, int nrows, int t) {
    int w = t >> 5;
    int l = t & 31;
    unsigned long long acc0[8], acc1[8];
#pragma unroll
    for (int j = 0; j < 8; j++) { acc0[j] = 0ull; acc1[j] = 0ull; }

#pragma unroll 8
    for (int k = 0; k < 64; k++) {
        float2 xv = *(const float2*)&Xs[k * 66 + 2 * l];
        const float4* wp = (const float4*)&Ws[k * 64 + w * 16];
        float4 wa = wp[0], wb = wp[1], wc = wp[2], wd = wp[3];
        unsigned long long x0 = pack2(xv.x, xv.x);
        unsigned long long x1 = pack2(xv.y, xv.y);
        unsigned long long wq[8] = {
            pack2(wa.x, wa.y), pack2(wa.z, wa.w),
            pack2(wb.x, wb.y), pack2(wb.z, wb.w),
            pack2(wc.x, wc.y), pack2(wc.z, wc.w),
            pack2(wd.x, wd.y), pack2(wd.z, wd.w)};
#pragma unroll
        for (int j = 0; j < 8; j++) {
            acc0[j] = ffma2(x0, wq[j], acc0[j]);
            acc1[j] = ffma2(x1, wq[j], acc1[j]);
        }
    }

#pragma unroll
    for (int rr = 0; rr < 2; rr++) {
        int gr = row0 + 2 * l + rr;
        if (gr >= nrows) continue;
        float dv = g_dinv[gr];
        unsigned long long* acc = rr ? acc1 : acc0;
        float o[16];
#pragma unroll
        for (int j = 0; j < 8; j++) {
            unpack2(acc[j], o[2 * j], o[2 * j + 1]);
            o[2 * j] *= dv; o[2 * j + 1] *= dv;
        }
        float4* gp = (float4*)&g_buf[(size_t)gr * FEAT + w * 16];
        float4* ap = (float4*)&g_agg[(size_t)gr * FEAT + w * 16];
#pragma unroll
        for (int j = 0; j < 4; j++) {
            float4 v = make_float4(o[4 * j], o[4 * j + 1], o[4 * j + 2], o[4 * j + 3]);
            gp[j] = v; ap[j] = v;
        }
    }
}

// standalone GEMM (layer 1, reads global X)
__global__ __launch_bounds__(128) void gemm_kernel(
    const float* __restrict__ X, int xstride,
    const float* __restrict__ W, int nrows)
{
    __shared__ float Ws[64 * 64];
    __shared__ float Xs[64 * 66];
    int t = threadIdx.x;
    int row0 = blockIdx.x * 64;
    for (int i = t; i < 4096; i += 128) Ws[i] = W[i];
    for (int i = t; i < 4096; i += 128) {
        int r = i >> 6, k = i & 63;
        int gr = row0 + r;
        Xs[k * 66 + r] = (gr < nrows) ? X[(size_t)gr * xstride + k] : 0.f;
    }
    __syncthreads();
    gemm_body(Ws, Xs, row0, nrows, t);
}

// fused: finalize layer L (relu + out write + colmax) feeding GEMM of layer L+1.
__global__ __launch_bounds__(128) void fused_fg_kernel(
    const float* __restrict__ bias, float* __restrict__ out, int colbase,
    const float* __restrict__ Wn, int N)
{
    __shared__ float Ws[64 * 64];
    __shared__ float Xs[64 * 66];
    __shared__ float sm[128];
    int t = threadIdx.x;
    int row0 = blockIdx.x * 64;

    for (int i = t; i < 4096; i += 128) Ws[i] = Wn[i];

    int c = t & 63;
    float b = bias[c];
    float mx = -FLT_MAX;
    for (int rr = t >> 6; rr < 64; rr += 2) {
        int gr = row0 + rr;
        float val = 0.f;
        if (gr < N) {
            val = fmaf(g_dinv[gr], g_agg[(size_t)gr * FEAT + c], b);
            val = fmaxf(val, 0.f);                       // fused layers always relu
            out[(size_t)gr * 192 + colbase + c] = val;
            mx = fmaxf(mx, val);
        }
        Xs[c * 66 + rr] = val;                           // transposed, ready for GEMM
    }
    sm[t] = mx;
    __syncthreads();                                     // covers Xs, Ws, sm
    if (t < 64) atomicMax(&g_gmax[colbase + t], ford(fmaxf(sm[t], sm[t + 64])));

    gemm_body(Ws, Xs, row0, N, t);
}

// ---------------- strip-mined segmented scatter ----------------
// Thread = (32-edge dst-sorted strip, float4 feature group), processed in 4
// chunks of 8. Loads within a chunk are independent (MLP=8); same-dst runs
// reduce in registers; red.global only at run boundaries.
__global__ __launch_bounds__(256) void scatter_kernel(int E) {
    int t = blockIdx.x * 256 + threadIdx.x;
    int grp = t & 15;
    int base = (t >> 4) * STRIP;
    if (base >= E) return;

    int curd = -1;
    float4 acc = make_float4(0.f, 0.f, 0.f, 0.f);

    for (int c0 = 0; c0 < STRIP; c0 += CHK) {
        int2 sd[CHK];
#pragma unroll
        for (int j = 0; j < CHK; j++) {
            int e = base + c0 + j;
            sd[j] = (e < E) ? g_epack[e] : make_int2(0, -1);
        }
        float4 v[CHK];
#pragma unroll
        for (int j = 0; j < CHK; j++) {
            v[j] = (sd[j].y >= 0)
                 ? *(const float4*)&g_buf[(size_t)sd[j].x * FEAT + grp * 4]
                 : make_float4(0.f, 0.f, 0.f, 0.f);
        }
#pragma unroll
        for (int j = 0; j < CHK; j++) {
            if (sd[j].y == curd) {
                acc.x += v[j].x; acc.y += v[j].y; acc.z += v[j].z; acc.w += v[j].w;
            } else {
                if (curd >= 0) redv4(&g_agg[(size_t)curd * FEAT + grp * 4], acc);
                curd = sd[j].y;
                acc = v[j];
            }
        }
    }
    if (curd >= 0) redv4(&g_agg[(size_t)curd * FEAT + grp * 4], acc);
}

// ---------------- finalize (last layer, no relu) + fused tail --------------
// Last block (fenced counter) emits graph_embedding + target logits and
// restores the g_gmax / g_done invariants.
__global__ __launch_bounds__(256) void finalize_kernel(
    const float* __restrict__ bias, float* __restrict__ out, int colbase,
    const float* __restrict__ fcW, const float* __restrict__ fcb,
    const int* __restrict__ tptr, int N)
{
    int t = threadIdx.x;
    int c = t & 63, rg = t >> 6;
    float b = bias[c];
    float mx = -FLT_MAX;
    for (int r = blockIdx.x * 4 + rg; r < N; r += gridDim.x * 4) {
        float v = fmaf(g_dinv[r], g_agg[(size_t)r * FEAT + c], b);
        out[(size_t)r * 192 + colbase + c] = v;
        mx = fmaxf(mx, v);
    }
    __shared__ float sm[256];
    sm[t] = mx;
    __syncthreads();
    if (rg == 0) {
        mx = fmaxf(fmaxf(sm[c], sm[64 + c]), fmaxf(sm[128 + c], sm[192 + c]));
        atomicMax(&g_gmax[colbase + c], ford(mx));
    }

    // last-block tail
    __shared__ int last;
    __threadfence();
    if (t == 0) last = (atomicAdd(&g_done, 1) == (int)gridDim.x - 1) ? 1 : 0;
    __syncthreads();
    if (last) {
        if (t < 192) {
            out[(size_t)N * 192 + t] = funord(g_gmax[t]);
            g_gmax[t] = 0u;                // restore invariant
        }
        if (t == 0) g_done = 0;            // restore invariant
        __syncthreads();
        if (t < 4) {
            int tn = *tptr;
            const float* emb = out + (size_t)tn * 192;
            float s = fcb[t];
            for (int k = 0; k < 192; k++) s += emb[k] * fcW[k * 4 + t];
            out[(size_t)N * 192 + 192 + t] = s;
        }
    }
}

// ---------------- launch ----------------
extern "C" void kernel_launch(void* const* d_in, const int* in_sizes, int n_in,
                              void* d_out, int out_size)
{
    const float* x   = (const float*)d_in[0];
    const void*  ei  = d_in[1];
    const int*   tgt = (const int*)d_in[3];
    const float* W1  = (const float*)d_in[4];
    const float* b1  = (const float*)d_in[5];
    const float* W2  = (const float*)d_in[6];
    const float* b2  = (const float*)d_in[7];
    const float* W3  = (const float*)d_in[8];
    const float* b3  = (const float*)d_in[9];
    const float* fcW = (const float*)d_in[10];
    const float* fcb = (const float*)d_in[11];
    float* out = (float*)d_out;

    int N = in_sizes[0] / FEAT;
    int E = in_sizes[1] / 2;
    int nscan = (N + 255) / 256;
    int e4blocks = ((E + 3) / 4 + 255) / 256;

    count_kernel<<<e4blocks, 256>>>(ei, E);
    scan1_kernel<<<nscan, 256>>>(N);
    scan23_kernel<<<nscan, 256>>>(N, nscan);
    fill_kernel<<<e4blocks, 256>>>(ei, E);

    int gemm_blocks = (N + 63) / 64;
    int nstrips = (E + STRIP - 1) / STRIP;
    int sc_blocks = (nstrips * 16 + 255) / 256;

    gemm_kernel<<<gemm_blocks, 128>>>(x, FEAT, W1, N);
    scatter_kernel<<<sc_blocks, 256>>>(E);
    fused_fg_kernel<<<gemm_blocks, 128>>>(b1, out, 0, W2, N);
    scatter_kernel<<<sc_blocks, 256>>>(E);
    fused_fg_kernel<<<gemm_blocks, 128>>>(b2, out, 64, W3, N);
    scatter_kernel<<<sc_blocks, 256>>>(E);
    finalize_kernel<<<512, 256>>>(b3, out, 128, fcW, fcb, tgt, N);
}